// round 1
// baseline (speedup 1.0000x reference)
#include <cuda_runtime.h>
#include <math.h>

#define NTOK 8192
#define DIM  1024
#define NEXP 8
#define DFF  4096
#define CAP  1280   // int(8192/8 * 1.25)

// ---------------- scratch (device globals; no allocation allowed) ----------
__device__ float g_h[(size_t)NEXP * CAP * DFF];   // expert hidden activations
__device__ int   g_eidx[NTOK];
__device__ float g_gate[NTOK];
__device__ int   g_kept[NTOK];
__device__ int   g_slot2tok[NEXP * CAP];
__device__ float g_probs_sum[NEXP];
__device__ int   g_count[NEXP];

// ---------------- init: zero the probability accumulators ------------------
__global__ void init_kernel() {
    if (threadIdx.x < NEXP) g_probs_sum[threadIdx.x] = 0.f;
}

// ---------------- router: logits, softmax, argmax, gate --------------------
// one warp per token; block-level reduction of prob sums
__global__ void router_kernel(const float* __restrict__ x,
                              const float* __restrict__ Wr) {
    __shared__ float s_sum[NEXP];
    if (threadIdx.x < NEXP) s_sum[threadIdx.x] = 0.f;
    __syncthreads();

    int gwarp = (blockIdx.x * blockDim.x + threadIdx.x) >> 5;
    int lane  = threadIdx.x & 31;
    if (gwarp < NTOK) {
        const float* xr = x + (size_t)gwarp * DIM;
        float acc[NEXP];
#pragma unroll
        for (int e = 0; e < NEXP; e++) acc[e] = 0.f;
        for (int d = lane; d < DIM; d += 32) {
            float xv = xr[d];
            const float* wr = Wr + d * NEXP;
#pragma unroll
            for (int e = 0; e < NEXP; e++) acc[e] += xv * wr[e];
        }
#pragma unroll
        for (int e = 0; e < NEXP; e++)
#pragma unroll
            for (int o = 16; o; o >>= 1)
                acc[e] += __shfl_xor_sync(0xffffffffu, acc[e], o);

        if (lane == 0) {
            float mx = acc[0]; int ai = 0;
#pragma unroll
            for (int e = 1; e < NEXP; e++)
                if (acc[e] > mx) { mx = acc[e]; ai = e; }
            float p[NEXP], den = 0.f;
#pragma unroll
            for (int e = 0; e < NEXP; e++) { p[e] = expf(acc[e] - mx); den += p[e]; }
            float inv = 1.f / den;
#pragma unroll
            for (int e = 0; e < NEXP; e++) {
                p[e] *= inv;
                atomicAdd(&s_sum[e], p[e]);
            }
            g_eidx[gwarp] = ai;
            g_gate[gwarp] = p[ai];
        }
    }
    __syncthreads();
    if (threadIdx.x < NEXP) atomicAdd(&g_probs_sum[threadIdx.x], s_sum[threadIdx.x]);
}

// ---------------- scan: order-exact per-expert positions + capacity --------
// single block, 1024 threads, 8 chunks of 1024 tokens
__global__ void scan_kernel() {
    __shared__ int sbase[NEXP];
    __shared__ int wpre[NEXP][32];
    __shared__ int ctot[NEXP];
    int tid = threadIdx.x, lane = tid & 31, wid = tid >> 5;

    for (int i = tid; i < NEXP * CAP; i += 1024) g_slot2tok[i] = NTOK;
    if (tid < NEXP) sbase[tid] = 0;
    __syncthreads();

    for (int c0 = 0; c0 < NTOK; c0 += 1024) {
        int tok = c0 + tid;
        int e = g_eidx[tok];
        int myrank = 0;
#pragma unroll
        for (int e2 = 0; e2 < NEXP; e2++) {
            unsigned m = __ballot_sync(0xffffffffu, e == e2);
            if (e == e2) myrank = __popc(m & ((1u << lane) - 1u));
            if (lane == 0) wpre[e2][wid] = __popc(m);
        }
        __syncthreads();
        if (wid < NEXP) {                       // warps 0..7 scan one expert each
            int v = wpre[wid][lane];
            int incl = v;
#pragma unroll
            for (int o = 1; o < 32; o <<= 1) {
                int t = __shfl_up_sync(0xffffffffu, incl, o);
                if (lane >= o) incl += t;
            }
            wpre[wid][lane] = incl - v;         // exclusive
            if (lane == 31) ctot[wid] = incl;
        }
        __syncthreads();
        int pos  = sbase[e] + wpre[e][wid] + myrank;
        int kept = (pos < CAP) ? 1 : 0;
        g_kept[tok] = kept;
        if (kept) g_slot2tok[e * CAP + pos] = tok;
        else      g_gate[tok] = 0.f;
        __syncthreads();
        if (tid < NEXP) sbase[tid] += ctot[tid];
        __syncthreads();
    }
    if (tid < NEXP) g_count[tid] = sbase[tid] < CAP ? sbase[tid] : CAP;
}

// ---------------- GELU (tanh approximation, matches jax.nn.gelu default) ---
__device__ __forceinline__ float gelu_tanh(float v) {
    const float k0 = 0.7978845608028654f;
    const float k1 = 0.044715f;
    float u = k0 * (v + k1 * v * v * v);
    return 0.5f * v * (1.f + tanhf(u));
}

// ---------------- GEMM1: h = gelu(gather(x)[slot] @ W1[e] + b1[e]) ---------
// 128x128x8 tiles, 256 threads, 8x8 microtile. A rows gathered via slot2tok.
__global__ __launch_bounds__(256, 2)
void gemm1_kernel(const float* __restrict__ x,
                  const float* __restrict__ W1,
                  const float* __restrict__ b1) {
    const int BM = 128, BN = 128, BK = 8;
    __shared__ float As[BK][BM];
    __shared__ float Bs[BK][BN];

    int e  = blockIdx.z;
    int mt = blockIdx.y;
    int nt = blockIdx.x;
    int tid = threadIdx.x;

    int arow = tid >> 1;
    int akq  = (tid & 1) * 4;
    int tok  = g_slot2tok[e * CAP + mt * BM + arow];
    const float* arow_ptr = (tok < NTOK) ? (x + (size_t)tok * DIM) : nullptr;

    int bk = tid >> 5;
    int bn = (tid & 31) * 4;
    const float* Bbase = W1 + (size_t)e * DIM * DFF + nt * BN + bn;

    float acc[8][8];
#pragma unroll
    for (int i = 0; i < 8; i++)
#pragma unroll
        for (int j = 0; j < 8; j++) acc[i][j] = 0.f;

    int tx = tid & 15, ty = tid >> 4;

    for (int k0 = 0; k0 < DIM; k0 += BK) {
        float4 av = arow_ptr ? *(const float4*)(arow_ptr + k0 + akq)
                             : make_float4(0.f, 0.f, 0.f, 0.f);
        float4 bv = *(const float4*)(Bbase + (size_t)(k0 + bk) * DFF);
        As[akq + 0][arow] = av.x;
        As[akq + 1][arow] = av.y;
        As[akq + 2][arow] = av.z;
        As[akq + 3][arow] = av.w;
        *(float4*)&Bs[bk][bn] = bv;
        __syncthreads();
#pragma unroll
        for (int k = 0; k < BK; k++) {
            float a[8], b[8];
            *(float4*)(a)     = *(float4*)&As[k][ty * 8];
            *(float4*)(a + 4) = *(float4*)&As[k][ty * 8 + 4];
            *(float4*)(b)     = *(float4*)&Bs[k][tx * 8];
            *(float4*)(b + 4) = *(float4*)&Bs[k][tx * 8 + 4];
#pragma unroll
            for (int i = 0; i < 8; i++)
#pragma unroll
                for (int j = 0; j < 8; j++) acc[i][j] += a[i] * b[j];
        }
        __syncthreads();
    }

    int gm = mt * BM + ty * 8;
    int gn = nt * BN + tx * 8;
    float bias[8];
#pragma unroll
    for (int j = 0; j < 8; j++) bias[j] = b1[e * DFF + gn + j];
    float* hbase = g_h + (size_t)e * CAP * DFF;
#pragma unroll
    for (int i = 0; i < 8; i++) {
        float4 v0, v1;
        v0.x = gelu_tanh(acc[i][0] + bias[0]);
        v0.y = gelu_tanh(acc[i][1] + bias[1]);
        v0.z = gelu_tanh(acc[i][2] + bias[2]);
        v0.w = gelu_tanh(acc[i][3] + bias[3]);
        v1.x = gelu_tanh(acc[i][4] + bias[4]);
        v1.y = gelu_tanh(acc[i][5] + bias[5]);
        v1.z = gelu_tanh(acc[i][6] + bias[6]);
        v1.w = gelu_tanh(acc[i][7] + bias[7]);
        float* dst = hbase + (size_t)(gm + i) * DFF + gn;
        *(float4*)(dst)     = v0;
        *(float4*)(dst + 4) = v1;
    }
}

// ---------------- passthrough for dropped tokens ---------------------------
__global__ void passthrough_kernel(const float* __restrict__ x,
                                   float* __restrict__ out) {
    int tok = blockIdx.x;
    if (g_kept[tok]) return;
    const float4* src = (const float4*)(x + (size_t)tok * DIM);
    float4* dst = (float4*)(out + (size_t)tok * DIM);
    dst[threadIdx.x] = src[threadIdx.x];
}

// ---------------- GEMM2: out[tok] = gate * (h @ W2[e] + b2[e]) -------------
__global__ __launch_bounds__(256, 2)
void gemm2_kernel(const float* __restrict__ W2,
                  const float* __restrict__ b2,
                  float* __restrict__ out) {
    const int BM = 128, BN = 128, BK = 8;
    __shared__ float As[BK][BM];
    __shared__ float Bs[BK][BN];

    int e  = blockIdx.z;
    int mt = blockIdx.y;
    int nt = blockIdx.x;
    int tid = threadIdx.x;

    int arow = tid >> 1;
    int akq  = (tid & 1) * 4;
    const float* arow_ptr = g_h + (size_t)(e * CAP + mt * BM + arow) * DFF;

    int bk = tid >> 5;
    int bn = (tid & 31) * 4;
    const float* Bbase = W2 + (size_t)e * DFF * DIM + nt * BN + bn;

    float acc[8][8];
#pragma unroll
    for (int i = 0; i < 8; i++)
#pragma unroll
        for (int j = 0; j < 8; j++) acc[i][j] = 0.f;

    int tx = tid & 15, ty = tid >> 4;

    for (int k0 = 0; k0 < DFF; k0 += BK) {
        float4 av = *(const float4*)(arow_ptr + k0 + akq);
        float4 bv = *(const float4*)(Bbase + (size_t)(k0 + bk) * DIM);
        As[akq + 0][arow] = av.x;
        As[akq + 1][arow] = av.y;
        As[akq + 2][arow] = av.z;
        As[akq + 3][arow] = av.w;
        *(float4*)&Bs[bk][bn] = bv;
        __syncthreads();
#pragma unroll
        for (int k = 0; k < BK; k++) {
            float a[8], b[8];
            *(float4*)(a)     = *(float4*)&As[k][ty * 8];
            *(float4*)(a + 4) = *(float4*)&As[k][ty * 8 + 4];
            *(float4*)(b)     = *(float4*)&Bs[k][tx * 8];
            *(float4*)(b + 4) = *(float4*)&Bs[k][tx * 8 + 4];
#pragma unroll
            for (int i = 0; i < 8; i++)
#pragma unroll
                for (int j = 0; j < 8; j++) acc[i][j] += a[i] * b[j];
        }
        __syncthreads();
    }

    int gm = mt * BM + ty * 8;
    int gn = nt * BN + tx * 8;
    float bias[8];
#pragma unroll
    for (int j = 0; j < 8; j++) bias[j] = b2[e * DIM + gn + j];
#pragma unroll
    for (int i = 0; i < 8; i++) {
        int tok = g_slot2tok[e * CAP + gm + i];
        if (tok >= NTOK) continue;
        float g = g_gate[tok];
        float4 v0, v1;
        v0.x = g * (acc[i][0] + bias[0]);
        v0.y = g * (acc[i][1] + bias[1]);
        v0.z = g * (acc[i][2] + bias[2]);
        v0.w = g * (acc[i][3] + bias[3]);
        v1.x = g * (acc[i][4] + bias[4]);
        v1.y = g * (acc[i][5] + bias[5]);
        v1.z = g * (acc[i][6] + bias[6]);
        v1.w = g * (acc[i][7] + bias[7]);
        float* dst = out + (size_t)tok * DIM + gn;
        *(float4*)(dst)     = v0;
        *(float4*)(dst + 4) = v1;
    }
}

// ---------------- aux loss --------------------------------------------------
__global__ void aux_kernel(float* __restrict__ out, int out_size) {
    if (out_size <= NTOK * DIM) return;
    float s = 0.f;
    for (int e = 0; e < NEXP; e++) {
        float frac = (float)g_count[e] / (float)NTOK;
        float pm   = g_probs_sum[e] / (float)NTOK;
        s += frac * pm;
    }
    out[NTOK * DIM] = 0.01f * (float)NEXP * s;
}

// ---------------- launch ----------------------------------------------------
extern "C" void kernel_launch(void* const* d_in, const int* in_sizes, int n_in,
                              void* d_out, int out_size) {
    const float* x  = (const float*)d_in[0];
    const float* Wr = (const float*)d_in[1];
    const float* W1 = (const float*)d_in[2];
    const float* b1 = (const float*)d_in[3];
    const float* W2 = (const float*)d_in[4];
    const float* b2 = (const float*)d_in[5];
    float* out = (float*)d_out;

    init_kernel<<<1, 32>>>();
    router_kernel<<<NTOK / 8, 256>>>(x, Wr);
    scan_kernel<<<1, 1024>>>();
    gemm1_kernel<<<dim3(DFF / 128, CAP / 128, NEXP), 256>>>(x, W1, b1);
    passthrough_kernel<<<NTOK, 256>>>(x, out);
    gemm2_kernel<<<dim3(DIM / 128, CAP / 128, NEXP), 256>>>(W2, b2, out);
    aux_kernel<<<1, 1>>>(out, out_size);
}

// round 5
// speedup vs baseline: 1.3396x; 1.3396x over previous
#include <cuda_runtime.h>
#include <cstdint>
#include <math.h>

#define NTOK 8192
#define DIM  1024
#define NEXP 8
#define DFF  4096
#define CAP  1280   // int(8192/8 * 1.25)

// ---------------- scratch (device globals; no allocation allowed) ----------
__device__ float g_h[(size_t)NEXP * CAP * DFF];   // expert hidden activations
__device__ int   g_eidx[NTOK];
__device__ float g_gate[NTOK];
__device__ int   g_kept[NTOK];
__device__ int   g_slot2tok[NEXP * CAP];
__device__ float g_probs_sum[NEXP];
__device__ int   g_count[NEXP];

// ---------------- init: zero the probability accumulators ------------------
__global__ void init_kernel() {
    if (threadIdx.x < NEXP) g_probs_sum[threadIdx.x] = 0.f;
}

// ---------------- router: logits, softmax, argmax, gate --------------------
__global__ void router_kernel(const float* __restrict__ x,
                              const float* __restrict__ Wr) {
    __shared__ float s_sum[NEXP];
    if (threadIdx.x < NEXP) s_sum[threadIdx.x] = 0.f;
    __syncthreads();

    int gwarp = (blockIdx.x * blockDim.x + threadIdx.x) >> 5;
    int lane  = threadIdx.x & 31;
    if (gwarp < NTOK) {
        const float* xr = x + (size_t)gwarp * DIM;
        float acc[NEXP];
#pragma unroll
        for (int e = 0; e < NEXP; e++) acc[e] = 0.f;
        for (int d = lane; d < DIM; d += 32) {
            float xv = xr[d];
            const float* wr = Wr + d * NEXP;
#pragma unroll
            for (int e = 0; e < NEXP; e++) acc[e] += xv * wr[e];
        }
#pragma unroll
        for (int e = 0; e < NEXP; e++)
#pragma unroll
            for (int o = 16; o; o >>= 1)
                acc[e] += __shfl_xor_sync(0xffffffffu, acc[e], o);

        if (lane == 0) {
            float mx = acc[0]; int ai = 0;
#pragma unroll
            for (int e = 1; e < NEXP; e++)
                if (acc[e] > mx) { mx = acc[e]; ai = e; }
            float p[NEXP], den = 0.f;
#pragma unroll
            for (int e = 0; e < NEXP; e++) { p[e] = expf(acc[e] - mx); den += p[e]; }
            float inv = 1.f / den;
#pragma unroll
            for (int e = 0; e < NEXP; e++) {
                p[e] *= inv;
                atomicAdd(&s_sum[e], p[e]);
            }
            g_eidx[gwarp] = ai;
            g_gate[gwarp] = p[ai];
        }
    }
    __syncthreads();
    if (threadIdx.x < NEXP) atomicAdd(&g_probs_sum[threadIdx.x], s_sum[threadIdx.x]);
}

// ---------------- scan: order-exact per-expert positions + capacity --------
__global__ void scan_kernel() {
    __shared__ int sbase[NEXP];
    __shared__ int wpre[NEXP][32];
    __shared__ int ctot[NEXP];
    int tid = threadIdx.x, lane = tid & 31, wid = tid >> 5;

    for (int i = tid; i < NEXP * CAP; i += 1024) g_slot2tok[i] = NTOK;
    if (tid < NEXP) sbase[tid] = 0;
    __syncthreads();

    for (int c0 = 0; c0 < NTOK; c0 += 1024) {
        int tok = c0 + tid;
        int e = g_eidx[tok];
        int myrank = 0;
#pragma unroll
        for (int e2 = 0; e2 < NEXP; e2++) {
            unsigned m = __ballot_sync(0xffffffffu, e == e2);
            if (e == e2) myrank = __popc(m & ((1u << lane) - 1u));
            if (lane == 0) wpre[e2][wid] = __popc(m);
        }
        __syncthreads();
        if (wid < NEXP) {
            int v = wpre[wid][lane];
            int incl = v;
#pragma unroll
            for (int o = 1; o < 32; o <<= 1) {
                int t = __shfl_up_sync(0xffffffffu, incl, o);
                if (lane >= o) incl += t;
            }
            wpre[wid][lane] = incl - v;
            if (lane == 31) ctot[wid] = incl;
        }
        __syncthreads();
        int pos  = sbase[e] + wpre[e][wid] + myrank;
        int kept = (pos < CAP) ? 1 : 0;
        g_kept[tok] = kept;
        if (kept) g_slot2tok[e * CAP + pos] = tok;
        else      g_gate[tok] = 0.f;
        __syncthreads();
        if (tid < NEXP) sbase[tid] += ctot[tid];
        __syncthreads();
    }
    if (tid < NEXP) g_count[tid] = sbase[tid] < CAP ? sbase[tid] : CAP;
}

// ---------------- GELU (tanh approximation) --------------------------------
__device__ __forceinline__ float gelu_tanh(float v) {
    const float k0 = 0.7978845608028654f;
    const float k1 = 0.044715f;
    float u = k0 * (v + k1 * v * v * v);
    return 0.5f * v * (1.f + tanhf(u));
}

// ============ tensor-core GEMM via 3xTF32 mma.sync (fp32 accuracy) ==========
// CTA tile 128(M) x 128(N) x 32(K).  256 threads = 8 warps (4m x 2n),
// warp tile 32x64 = 2 m-frags x 8 n-frags of m16n8k8.
// Each fp32 operand is split hi/lo (hi = tf32 rounding); product computed as
// hi*hi + lo*hi + hi*lo via 3 mma.sync into the same fp32 accumulator.
// A smem: [128][36] K-major; B smem: [32][132] N-major.  3-stage cp.async.
// MODE 0: A = gathered x rows -> epilogue gelu(v+b1) into g_h
// MODE 1: A = g_h rows        -> epilogue gate*(v+b2) scattered to out

#define ASTR 36
#define BSTR 132
#define A_FLOATS (128 * ASTR)                // 4608
#define STAGE_FLOATS (A_FLOATS + 32 * BSTR)  // 8832 floats = 35328 B
#define NSTAGE 3
#define GEMM_SMEM (STAGE_FLOATS * NSTAGE * 4)   // 105984 B

__device__ __forceinline__ void cpa16(uint32_t dst, const void* src, int src_size) {
    asm volatile("cp.async.cg.shared.global [%0], [%1], 16, %2;"
                 :: "r"(dst), "l"(src), "r"(src_size));
}
__device__ __forceinline__ void cpa_commit() {
    asm volatile("cp.async.commit_group;" ::: "memory");
}
template<int N> __device__ __forceinline__ void cpa_wait() {
    asm volatile("cp.async.wait_group %0;" :: "n"(N) : "memory");
}

__device__ __forceinline__ void ldsm_x4(uint32_t& r0, uint32_t& r1,
                                        uint32_t& r2, uint32_t& r3, uint32_t a) {
    asm volatile("ldmatrix.sync.aligned.m8n8.x4.shared.b16 {%0,%1,%2,%3}, [%4];"
                 : "=r"(r0), "=r"(r1), "=r"(r2), "=r"(r3) : "r"(a));
}

__device__ __forceinline__ void mma_tf32(float* d, const uint32_t* a,
                                         uint32_t b0, uint32_t b1) {
    asm volatile(
        "mma.sync.aligned.m16n8k8.row.col.f32.tf32.tf32.f32 "
        "{%0,%1,%2,%3}, {%4,%5,%6,%7}, {%8,%9}, {%0,%1,%2,%3};"
        : "+f"(d[0]), "+f"(d[1]), "+f"(d[2]), "+f"(d[3])
        : "r"(a[0]), "r"(a[1]), "r"(a[2]), "r"(a[3]), "r"(b0), "r"(b1));
}

// hi = round-to-nearest tf32 of x (bit pattern); lo = x - hi
__device__ __forceinline__ uint32_t tf32_hi(float x) {
    uint32_t r;
    asm("cvt.rna.tf32.f32 %0, %1;" : "=r"(r) : "f"(x));
    return r;
}

template<int KDIM, int NB, int MODE>
__global__ __launch_bounds__(256, 1)
void gemm_mma(const float* __restrict__ Ax,
              const float* __restrict__ W,
              const float* __restrict__ bias,
              float* __restrict__ out) {
    extern __shared__ __align__(16) float smem[];
    const int e  = blockIdx.z;
    const int mt = blockIdx.y;
    const int nt = blockIdx.x;
    const int tid = threadIdx.x;
    const int lane = tid & 31;
    const int wid  = tid >> 5;
    const int wm = (wid & 3) * 32;        // warp m offset
    const int wn = (wid >> 2) * 64;       // warp n offset

    // ---- per-thread global source pointers ----
    int arow = tid >> 1;                  // A tile row owned (2 thr/row)
    const float* aptr;
    int asz = 16;
    if (MODE == 0) {
        int tok = g_slot2tok[e * CAP + mt * 128 + arow];
        if (tok >= NTOK) { tok = 0; asz = 0; }       // zero-fill dropped slot
        aptr = Ax + (size_t)tok * DIM + (tid & 1) * 16;
    } else {
        aptr = g_h + (size_t)(e * CAP + mt * 128 + arow) * KDIM + (tid & 1) * 16;
    }
    const float* bptr = W + (size_t)e * KDIM * NB
                          + (size_t)(tid >> 3) * NB + nt * 128 + (tid & 7) * 16;

    const uint32_t smem_b = (uint32_t)__cvta_generic_to_shared(smem);
    const uint32_t sa_off = ((tid >> 1) * ASTR + (tid & 1) * 16) * 4;
    const uint32_t sb_off = (A_FLOATS + (tid >> 3) * BSTR + (tid & 7) * 16) * 4;

    const int NC = KDIM / 32;

    // ---- stage loader ----
    auto load_stage = [&](int s, int k0) {
        uint32_t base = smem_b + s * STAGE_FLOATS * 4;
        const float* ap = aptr + k0;
        const float* bp = bptr + (size_t)k0 * NB;
#pragma unroll
        for (int i = 0; i < 4; i++) cpa16(base + sa_off + i * 16, ap + i * 4, asz);
#pragma unroll
        for (int i = 0; i < 4; i++) cpa16(base + sb_off + i * 16, bp + i * 4, 16);
        cpa_commit();
    };

    load_stage(0, 0);
    load_stage(1, 32);

    // ---- fragment addressing (per-lane, stage-invariant parts) ----
    const int a_row = (lane & 7) + ((lane >> 3) & 1) * 8;
    const int a_col = ((lane >> 4) & 1) * 4;
    const int b_k = lane & 3;
    const int b_n = wn + (lane >> 2);

    float acc[2][8][4];
#pragma unroll
    for (int mi = 0; mi < 2; mi++)
#pragma unroll
        for (int nf = 0; nf < 8; nf++)
#pragma unroll
            for (int q = 0; q < 4; q++) acc[mi][nf][q] = 0.f;

    for (int c = 0; c < NC; c++) {
        cpa_wait<1>();
        __syncthreads();
        if (c + 2 < NC) load_stage((c + 2) % NSTAGE, (c + 2) * 32);
        else            cpa_commit();

        int buf = c % NSTAGE;
        const float* Bs = smem + buf * STAGE_FLOATS + A_FLOATS;
        uint32_t a_base = smem_b + buf * STAGE_FLOATS * 4;

#pragma unroll
        for (int ks = 0; ks < 4; ks++) {
            // --- load + split A fragments ---
            uint32_t a_hi[2][4], a_lo[2][4];
#pragma unroll
            for (int mi = 0; mi < 2; mi++) {
                uint32_t raw[4];
                uint32_t addr = a_base +
                    ((wm + mi * 16 + a_row) * ASTR + ks * 8 + a_col) * 4;
                ldsm_x4(raw[0], raw[1], raw[2], raw[3], addr);
#pragma unroll
                for (int j = 0; j < 4; j++) {
                    float af = __uint_as_float(raw[j]);
                    uint32_t h = tf32_hi(af);
                    a_hi[mi][j] = h;
                    a_lo[mi][j] = __float_as_uint(af - __uint_as_float(h));
                }
            }
            // --- B fragments in groups of 4 nf to bound registers ---
#pragma unroll
            for (int nh = 0; nh < 2; nh++) {
                uint32_t bh[4][2], bl[4][2];
#pragma unroll
                for (int n2 = 0; n2 < 4; n2++) {
                    int k0 = ks * 8 + b_k;
                    int n  = b_n + (nh * 4 + n2) * 8;
                    float b0f = Bs[k0 * BSTR + n];
                    float b1f = Bs[(k0 + 4) * BSTR + n];
                    uint32_t h0 = tf32_hi(b0f), h1 = tf32_hi(b1f);
                    bh[n2][0] = h0;
                    bh[n2][1] = h1;
                    bl[n2][0] = __float_as_uint(b0f - __uint_as_float(h0));
                    bl[n2][1] = __float_as_uint(b1f - __uint_as_float(h1));
                }
#pragma unroll
                for (int mi = 0; mi < 2; mi++)
#pragma unroll
                    for (int n2 = 0; n2 < 4; n2++) {
                        float* d = acc[mi][nh * 4 + n2];
                        mma_tf32(d, a_lo[mi], bh[n2][0], bh[n2][1]);
                        mma_tf32(d, a_hi[mi], bl[n2][0], bl[n2][1]);
                        mma_tf32(d, a_hi[mi], bh[n2][0], bh[n2][1]);
                    }
            }
        }
        __syncthreads();
    }

    // ---- epilogue ----
    const float* bias_p = bias + e * NB + nt * 128;
#pragma unroll
    for (int mi = 0; mi < 2; mi++) {
#pragma unroll
        for (int rr = 0; rr < 2; rr++) {
            int lrow = wm + mi * 16 + (lane >> 2) + rr * 8;   // row in tile
            int slot = e * CAP + mt * 128 + lrow;
            if (MODE == 0) {
                float* hrow = g_h + (size_t)slot * DFF + nt * 128;
#pragma unroll
                for (int nf = 0; nf < 8; nf++) {
                    int cn = wn + nf * 8 + (lane & 3) * 2;
                    float2 v;
                    v.x = gelu_tanh(acc[mi][nf][rr * 2 + 0] + bias_p[cn]);
                    v.y = gelu_tanh(acc[mi][nf][rr * 2 + 1] + bias_p[cn + 1]);
                    *(float2*)(hrow + cn) = v;
                }
            } else {
                int tok = g_slot2tok[slot];
                if (tok < NTOK) {
                    float gt = g_gate[tok];
                    float* orow = out + (size_t)tok * DIM + nt * 128;
#pragma unroll
                    for (int nf = 0; nf < 8; nf++) {
                        int cn = wn + nf * 8 + (lane & 3) * 2;
                        float2 v;
                        v.x = gt * (acc[mi][nf][rr * 2 + 0] + bias_p[cn]);
                        v.y = gt * (acc[mi][nf][rr * 2 + 1] + bias_p[cn + 1]);
                        *(float2*)(orow + cn) = v;
                    }
                }
            }
        }
    }
}

// ---------------- passthrough for dropped tokens ---------------------------
__global__ void passthrough_kernel(const float* __restrict__ x,
                                   float* __restrict__ out) {
    int tok = blockIdx.x;
    if (g_kept[tok]) return;
    const float4* src = (const float4*)(x + (size_t)tok * DIM);
    float4* dst = (float4*)(out + (size_t)tok * DIM);
    dst[threadIdx.x] = src[threadIdx.x];
}

// ---------------- aux loss --------------------------------------------------
__global__ void aux_kernel(float* __restrict__ out, int out_size) {
    if (out_size <= NTOK * DIM) return;
    float s = 0.f;
    for (int e = 0; e < NEXP; e++) {
        float frac = (float)g_count[e] / (float)NTOK;
        float pm   = g_probs_sum[e] / (float)NTOK;
        s += frac * pm;
    }
    out[NTOK * DIM] = 0.01f * (float)NEXP * s;
}

// ---------------- launch ----------------------------------------------------
extern "C" void kernel_launch(void* const* d_in, const int* in_sizes, int n_in,
                              void* d_out, int out_size) {
    const float* x  = (const float*)d_in[0];
    const float* Wr = (const float*)d_in[1];
    const float* W1 = (const float*)d_in[2];
    const float* b1 = (const float*)d_in[3];
    const float* W2 = (const float*)d_in[4];
    const float* b2 = (const float*)d_in[5];
    float* out = (float*)d_out;

    cudaFuncSetAttribute(gemm_mma<DIM, DFF, 0>,
                         cudaFuncAttributeMaxDynamicSharedMemorySize, GEMM_SMEM);
    cudaFuncSetAttribute(gemm_mma<DFF, DIM, 1>,
                         cudaFuncAttributeMaxDynamicSharedMemorySize, GEMM_SMEM);

    init_kernel<<<1, 32>>>();
    router_kernel<<<NTOK / 8, 256>>>(x, Wr);
    scan_kernel<<<1, 1024>>>();

    // GEMM1: h = gelu(gather(x) @ W1 + b1)   [M=CAP, N=DFF, K=DIM]
    gemm_mma<DIM, DFF, 0><<<dim3(DFF / 128, CAP / 128, NEXP), 256, GEMM_SMEM>>>(
        x, W1, b1, nullptr);

    passthrough_kernel<<<NTOK, 256>>>(x, out);

    // GEMM2: out[tok] = gate * (h @ W2 + b2) [M=CAP, N=DIM, K=DFF]
    gemm_mma<DFF, DIM, 1><<<dim3(DIM / 128, CAP / 128, NEXP), 256, GEMM_SMEM>>>(
        nullptr, W2, b2, out);

    aux_kernel<<<1, 1>>>(out, out_size);
}

// round 7
// speedup vs baseline: 2.2590x; 1.6864x over previous
#include <cuda_runtime.h>
#include <cuda_bf16.h>
#include <cstdint>
#include <math.h>

#define NTOK 8192
#define DIM  1024
#define NEXP 8
#define DFF  4096
#define CAP  1280   // int(8192/8 * 1.25)

// ---------------- scratch (device globals; no allocation allowed) ----------
__device__ __nv_bfloat16 g_xh[(size_t)NTOK * DIM];
__device__ __nv_bfloat16 g_xl[(size_t)NTOK * DIM];
__device__ __nv_bfloat16 g_W1h[(size_t)NEXP * DIM * DFF];
__device__ __nv_bfloat16 g_W1l[(size_t)NEXP * DIM * DFF];
__device__ __nv_bfloat16 g_W2h[(size_t)NEXP * DFF * DIM];
__device__ __nv_bfloat16 g_W2l[(size_t)NEXP * DFF * DIM];
__device__ __nv_bfloat16 g_hh[(size_t)NEXP * CAP * DFF];
__device__ __nv_bfloat16 g_hl[(size_t)NEXP * CAP * DFF];
__device__ int   g_eidx[NTOK];
__device__ float g_gate[NTOK];
__device__ int   g_kept[NTOK];
__device__ int   g_slot2tok[NEXP * CAP];
__device__ float g_probs_sum[NEXP];
__device__ int   g_count[NEXP];

// ---------------- init ------------------------------------------------------
__global__ void init_kernel() {
    if (threadIdx.x < NEXP) g_probs_sum[threadIdx.x] = 0.f;
}

// ---------------- router: logits, softmax, argmax, gate --------------------
__global__ void router_kernel(const float* __restrict__ x,
                              const float* __restrict__ Wr) {
    __shared__ float s_sum[NEXP];
    if (threadIdx.x < NEXP) s_sum[threadIdx.x] = 0.f;
    __syncthreads();

    int gwarp = (blockIdx.x * blockDim.x + threadIdx.x) >> 5;
    int lane  = threadIdx.x & 31;
    if (gwarp < NTOK) {
        const float* xr = x + (size_t)gwarp * DIM;
        float acc[NEXP];
#pragma unroll
        for (int e = 0; e < NEXP; e++) acc[e] = 0.f;
        for (int d = lane; d < DIM; d += 32) {
            float xv = xr[d];
            const float* wr = Wr + d * NEXP;
#pragma unroll
            for (int e = 0; e < NEXP; e++) acc[e] += xv * wr[e];
        }
#pragma unroll
        for (int e = 0; e < NEXP; e++)
#pragma unroll
            for (int o = 16; o; o >>= 1)
                acc[e] += __shfl_xor_sync(0xffffffffu, acc[e], o);

        if (lane == 0) {
            float mx = acc[0]; int ai = 0;
#pragma unroll
            for (int e = 1; e < NEXP; e++)
                if (acc[e] > mx) { mx = acc[e]; ai = e; }
            float p[NEXP], den = 0.f;
#pragma unroll
            for (int e = 0; e < NEXP; e++) { p[e] = expf(acc[e] - mx); den += p[e]; }
            float inv = 1.f / den;
#pragma unroll
            for (int e = 0; e < NEXP; e++) {
                p[e] *= inv;
                atomicAdd(&s_sum[e], p[e]);
            }
            g_eidx[gwarp] = ai;
            g_gate[gwarp] = p[ai];
        }
    }
    __syncthreads();
    if (threadIdx.x < NEXP) atomicAdd(&g_probs_sum[threadIdx.x], s_sum[threadIdx.x]);
}

// ---------------- scan: order-exact per-expert positions + capacity --------
__global__ void scan_kernel() {
    __shared__ int sbase[NEXP];
    __shared__ int wpre[NEXP][32];
    __shared__ int ctot[NEXP];
    int tid = threadIdx.x, lane = tid & 31, wid = tid >> 5;

    for (int i = tid; i < NEXP * CAP; i += 1024) g_slot2tok[i] = NTOK;
    if (tid < NEXP) sbase[tid] = 0;
    __syncthreads();

    for (int c0 = 0; c0 < NTOK; c0 += 1024) {
        int tok = c0 + tid;
        int e = g_eidx[tok];
        int myrank = 0;
#pragma unroll
        for (int e2 = 0; e2 < NEXP; e2++) {
            unsigned m = __ballot_sync(0xffffffffu, e == e2);
            if (e == e2) myrank = __popc(m & ((1u << lane) - 1u));
            if (lane == 0) wpre[e2][wid] = __popc(m);
        }
        __syncthreads();
        if (wid < NEXP) {
            int v = wpre[wid][lane];
            int incl = v;
#pragma unroll
            for (int o = 1; o < 32; o <<= 1) {
                int t = __shfl_up_sync(0xffffffffu, incl, o);
                if (lane >= o) incl += t;
            }
            wpre[wid][lane] = incl - v;
            if (lane == 31) ctot[wid] = incl;
        }
        __syncthreads();
        int pos  = sbase[e] + wpre[e][wid] + myrank;
        int kept = (pos < CAP) ? 1 : 0;
        g_kept[tok] = kept;
        if (kept) g_slot2tok[e * CAP + pos] = tok;
        else      g_gate[tok] = 0.f;
        __syncthreads();
        if (tid < NEXP) sbase[tid] += ctot[tid];
        __syncthreads();
    }
    if (tid < NEXP) g_count[tid] = sbase[tid] < CAP ? sbase[tid] : CAP;
}

// ---------------- bf16 split: v = hi + lo (both rn) ------------------------
__device__ __forceinline__ void bf16_split(float v, __nv_bfloat16& h, __nv_bfloat16& l) {
    h = __float2bfloat16(v);
    l = __float2bfloat16(v - __bfloat162float(h));
}

// elementwise split kernel: 4 elems/thread
__global__ void split_kernel(const float* __restrict__ src,
                             __nv_bfloat16* __restrict__ dh,
                             __nv_bfloat16* __restrict__ dl, size_t n4) {
    size_t i = (size_t)blockIdx.x * blockDim.x + threadIdx.x;
    if (i >= n4) return;
    float4 v = ((const float4*)src)[i];
    __nv_bfloat16 h0, h1, h2, h3, l0, l1, l2, l3;
    bf16_split(v.x, h0, l0);
    bf16_split(v.y, h1, l1);
    bf16_split(v.z, h2, l2);
    bf16_split(v.w, h3, l3);
    ((__nv_bfloat162*)dh)[i * 2]     = __nv_bfloat162(h0, h1);
    ((__nv_bfloat162*)dh)[i * 2 + 1] = __nv_bfloat162(h2, h3);
    ((__nv_bfloat162*)dl)[i * 2]     = __nv_bfloat162(l0, l1);
    ((__nv_bfloat162*)dl)[i * 2 + 1] = __nv_bfloat162(l2, l3);
}

// ---------------- GELU (tanh approximation) --------------------------------
__device__ __forceinline__ float gelu_tanh(float v) {
    const float k0 = 0.7978845608028654f;
    const float k1 = 0.044715f;
    float u = k0 * (v + k1 * v * v * v);
    return 0.5f * v * (1.f + tanhf(u));
}

// ============ tensor-core GEMM via 3x bf16 mma.sync (split operands) ========
// CTA tile 128(M) x 128(N) x 32(K). 256 threads = 8 warps (4m x 2n),
// warp tile 32x64 = 2 m-frags x 8 n-frags of m16n8k16.
// a*b ~= a0*b0 + a0*b1 + a1*b0 with a0,b0 bf16(rn) and a1,b1 residuals.
// Smem (bf16, padded): A_hi/A_lo [128][40], B_hi/B_lo [32][136]. 3-stage cp.async.
// MODE 0: A = gathered split-x rows -> epilogue gelu(v+b1) split into g_hh/g_hl
// MODE 1: A = split-h rows          -> epilogue gate*(v+b2) scattered to out

#define ASTR 40     // bf16 per A row (32 + 8 pad)
#define BSTR 136    // bf16 per B row (128 + 8 pad)
#define OFF_AH 0
#define OFF_AL (128 * ASTR)                  // 5120
#define OFF_BH (2 * 128 * ASTR)              // 10240
#define OFF_BL (2 * 128 * ASTR + 32 * BSTR)  // 14592
#define STAGE_ELEMS (2 * 128 * ASTR + 2 * 32 * BSTR)   // 18944 bf16 = 37888 B
#define NSTAGE 3
#define GEMM_SMEM (STAGE_ELEMS * NSTAGE * 2)           // 113664 B

__device__ __forceinline__ void cpa16(uint32_t dst, const void* src, int src_size) {
    asm volatile("cp.async.cg.shared.global [%0], [%1], 16, %2;"
                 :: "r"(dst), "l"(src), "r"(src_size));
}
__device__ __forceinline__ void cpa_commit() {
    asm volatile("cp.async.commit_group;" ::: "memory");
}
template<int N> __device__ __forceinline__ void cpa_wait() {
    asm volatile("cp.async.wait_group %0;" :: "n"(N) : "memory");
}

__device__ __forceinline__ void ldsm_x4(uint32_t* r, uint32_t a) {
    asm volatile("ldmatrix.sync.aligned.m8n8.x4.shared.b16 {%0,%1,%2,%3}, [%4];"
                 : "=r"(r[0]), "=r"(r[1]), "=r"(r[2]), "=r"(r[3]) : "r"(a));
}
__device__ __forceinline__ void ldsm_x4_t(uint32_t* r, uint32_t a) {
    asm volatile("ldmatrix.sync.aligned.m8n8.x4.trans.shared.b16 {%0,%1,%2,%3}, [%4];"
                 : "=r"(r[0]), "=r"(r[1]), "=r"(r[2]), "=r"(r[3]) : "r"(a));
}

__device__ __forceinline__ void mma_bf16(float* d, const uint32_t* a, const uint32_t* b) {
    asm volatile(
        "mma.sync.aligned.m16n8k16.row.col.f32.bf16.bf16.f32 "
        "{%0,%1,%2,%3}, {%4,%5,%6,%7}, {%8,%9}, {%0,%1,%2,%3};"
        : "+f"(d[0]), "+f"(d[1]), "+f"(d[2]), "+f"(d[3])
        : "r"(a[0]), "r"(a[1]), "r"(a[2]), "r"(a[3]), "r"(b[0]), "r"(b[1]));
}

template<int KDIM, int NB, int MODE>
__global__ __launch_bounds__(256, 1)
void gemm_mma(const float* __restrict__ bias, float* __restrict__ out) {
    extern __shared__ __align__(16) __nv_bfloat16 smem[];
    const int e  = blockIdx.z;
    const int mt = blockIdx.y;
    const int nt = blockIdx.x;
    const int tid = threadIdx.x;
    const int lane = tid & 31;
    const int wid  = tid >> 5;
    const int wm = (wid & 3) * 32;        // warp m offset
    const int wn = (wid >> 2) * 64;       // warp n offset

    // ---- per-thread global source pointers (A: 2 thr/row, B: 8 thr/row) ----
    const int arow = tid >> 1;
    const int ahalf = tid & 1;            // 16-bf16 half of the 32-chunk
    const __nv_bfloat16 *aph, *apl;
    int asz = 16;
    if (MODE == 0) {
        int tok = g_slot2tok[e * CAP + mt * 128 + arow];
        if (tok >= NTOK) { tok = 0; asz = 0; }       // zero-fill dropped slot
        aph = g_xh + (size_t)tok * DIM + ahalf * 16;
        apl = g_xl + (size_t)tok * DIM + ahalf * 16;
    } else {
        size_t off = (size_t)(e * CAP + mt * 128 + arow) * KDIM + ahalf * 16;
        aph = g_hh + off;
        apl = g_hl + off;
    }
    const size_t boff = (size_t)e * KDIM * NB + (size_t)(tid >> 3) * NB
                      + nt * 128 + (tid & 7) * 16;
    const __nv_bfloat16* bph = ((MODE == 0) ? g_W1h : g_W2h) + boff;
    const __nv_bfloat16* bpl = ((MODE == 0) ? g_W1l : g_W2l) + boff;

    const uint32_t smem_b = (uint32_t)__cvta_generic_to_shared(smem);
    const uint32_t sa = (arow * ASTR + ahalf * 16) * 2;           // bytes
    const uint32_t sb = ((tid >> 3) * BSTR + (tid & 7) * 16) * 2; // bytes

    const int NC = KDIM / 32;

    auto load_stage = [&](int s, int k0) {
        uint32_t base = smem_b + s * STAGE_ELEMS * 2;
        cpa16(base + OFF_AH * 2 + sa,      aph + k0, asz);
        cpa16(base + OFF_AH * 2 + sa + 16, aph + k0 + 8, asz);
        cpa16(base + OFF_AL * 2 + sa,      apl + k0, asz);
        cpa16(base + OFF_AL * 2 + sa + 16, apl + k0 + 8, asz);
        const __nv_bfloat16* bh = bph + (size_t)k0 * NB;
        const __nv_bfloat16* bl = bpl + (size_t)k0 * NB;
        cpa16(base + OFF_BH * 2 + sb,      bh, 16);
        cpa16(base + OFF_BH * 2 + sb + 16, bh + 8, 16);
        cpa16(base + OFF_BL * 2 + sb,      bl, 16);
        cpa16(base + OFF_BL * 2 + sb + 16, bl + 8, 16);
        cpa_commit();
    };

    load_stage(0, 0);
    load_stage(1, 32);

    // ---- ldmatrix lane addressing (stage-invariant parts) ----
    const int lr = lane & 7, lg = lane >> 3;
    // A: row = wm + mi*16 + (lg&1)*8 + lr ; col = ks*16 + (lg>>1)*8
    const int a_row = wm + (lg & 1) * 8 + lr;
    const int a_col = (lg >> 1) * 8;
    // B(trans): row(k) = ks*16 + (lg&1)*8 + lr ; col(n) = wn + nf2*16 + (lg>>1)*8
    const int b_row = (lg & 1) * 8 + lr;
    const int b_col = wn + (lg >> 1) * 8;

    float acc[2][8][4];
#pragma unroll
    for (int mi = 0; mi < 2; mi++)
#pragma unroll
        for (int nf = 0; nf < 8; nf++)
#pragma unroll
            for (int q = 0; q < 4; q++) acc[mi][nf][q] = 0.f;

    for (int c = 0; c < NC; c++) {
        cpa_wait<1>();
        __syncthreads();
        if (c + 2 < NC) load_stage((c + 2) % NSTAGE, (c + 2) * 32);
        else            cpa_commit();

        uint32_t base = smem_b + (c % NSTAGE) * STAGE_ELEMS * 2;

#pragma unroll
        for (int ks = 0; ks < 2; ks++) {
            uint32_t ah[2][4], al[2][4], bh[8][2], bl[8][2];
#pragma unroll
            for (int mi = 0; mi < 2; mi++) {
                uint32_t addr = base +
                    ((a_row + mi * 16) * ASTR + ks * 16 + a_col) * 2;
                ldsm_x4(ah[mi], addr + OFF_AH * 2);
                ldsm_x4(al[mi], addr + OFF_AL * 2);
            }
#pragma unroll
            for (int nf2 = 0; nf2 < 4; nf2++) {
                uint32_t addr = base +
                    ((ks * 16 + b_row) * BSTR + b_col + nf2 * 16) * 2;
                uint32_t rh[4], rl[4];
                ldsm_x4_t(rh, addr + OFF_BH * 2);
                ldsm_x4_t(rl, addr + OFF_BL * 2);
                bh[nf2 * 2][0] = rh[0]; bh[nf2 * 2][1] = rh[1];
                bh[nf2 * 2 + 1][0] = rh[2]; bh[nf2 * 2 + 1][1] = rh[3];
                bl[nf2 * 2][0] = rl[0]; bl[nf2 * 2][1] = rl[1];
                bl[nf2 * 2 + 1][0] = rl[2]; bl[nf2 * 2 + 1][1] = rl[3];
            }
            // term-major: 16 independent MMAs between accumulator reuses
#pragma unroll
            for (int mi = 0; mi < 2; mi++)
#pragma unroll
                for (int nf = 0; nf < 8; nf++)
                    mma_bf16(acc[mi][nf], ah[mi], bh[nf]);
#pragma unroll
            for (int mi = 0; mi < 2; mi++)
#pragma unroll
                for (int nf = 0; nf < 8; nf++)
                    mma_bf16(acc[mi][nf], ah[mi], bl[nf]);
#pragma unroll
            for (int mi = 0; mi < 2; mi++)
#pragma unroll
                for (int nf = 0; nf < 8; nf++)
                    mma_bf16(acc[mi][nf], al[mi], bh[nf]);
        }
        __syncthreads();
    }

    // ---- epilogue ----
    const float* bias_p = bias + e * NB + nt * 128;
#pragma unroll
    for (int mi = 0; mi < 2; mi++) {
#pragma unroll
        for (int rr = 0; rr < 2; rr++) {
            int lrow = wm + mi * 16 + (lane >> 2) + rr * 8;   // row in tile
            int slot = e * CAP + mt * 128 + lrow;
            if (MODE == 0) {
                size_t rowoff = (size_t)slot * DFF + nt * 128;
#pragma unroll
                for (int nf = 0; nf < 8; nf++) {
                    int cn = wn + nf * 8 + (lane & 3) * 2;
                    float v0 = gelu_tanh(acc[mi][nf][rr * 2 + 0] + bias_p[cn]);
                    float v1 = gelu_tanh(acc[mi][nf][rr * 2 + 1] + bias_p[cn + 1]);
                    __nv_bfloat16 h0, h1, l0, l1;
                    bf16_split(v0, h0, l0);
                    bf16_split(v1, h1, l1);
                    *(__nv_bfloat162*)(g_hh + rowoff + cn) = __nv_bfloat162(h0, h1);
                    *(__nv_bfloat162*)(g_hl + rowoff + cn) = __nv_bfloat162(l0, l1);
                }
            } else {
                int tok = g_slot2tok[slot];
                if (tok < NTOK) {
                    float gt = g_gate[tok];
                    float* orow = out + (size_t)tok * DIM + nt * 128;
#pragma unroll
                    for (int nf = 0; nf < 8; nf++) {
                        int cn = wn + nf * 8 + (lane & 3) * 2;
                        float2 v;
                        v.x = gt * (acc[mi][nf][rr * 2 + 0] + bias_p[cn]);
                        v.y = gt * (acc[mi][nf][rr * 2 + 1] + bias_p[cn + 1]);
                        *(float2*)(orow + cn) = v;
                    }
                }
            }
        }
    }
}

// ---------------- passthrough for dropped tokens ---------------------------
__global__ void passthrough_kernel(const float* __restrict__ x,
                                   float* __restrict__ out) {
    int tok = blockIdx.x;
    if (g_kept[tok]) return;
    const float4* src = (const float4*)(x + (size_t)tok * DIM);
    float4* dst = (float4*)(out + (size_t)tok * DIM);
    dst[threadIdx.x] = src[threadIdx.x];
}

// ---------------- aux loss --------------------------------------------------
__global__ void aux_kernel(float* __restrict__ out, int out_size) {
    if (out_size <= NTOK * DIM) return;
    float s = 0.f;
    for (int e = 0; e < NEXP; e++) {
        float frac = (float)g_count[e] / (float)NTOK;
        float pm   = g_probs_sum[e] / (float)NTOK;
        s += frac * pm;
    }
    out[NTOK * DIM] = 0.01f * (float)NEXP * s;
}

// ---------------- launch ----------------------------------------------------
extern "C" void kernel_launch(void* const* d_in, const int* in_sizes, int n_in,
                              void* d_out, int out_size) {
    const float* x  = (const float*)d_in[0];
    const float* Wr = (const float*)d_in[1];
    const float* W1 = (const float*)d_in[2];
    const float* b1 = (const float*)d_in[3];
    const float* W2 = (const float*)d_in[4];
    const float* b2 = (const float*)d_in[5];
    float* out = (float*)d_out;

    cudaFuncSetAttribute(gemm_mma<DIM, DFF, 0>,
                         cudaFuncAttributeMaxDynamicSharedMemorySize, GEMM_SMEM);
    cudaFuncSetAttribute(gemm_mma<DFF, DIM, 1>,
                         cudaFuncAttributeMaxDynamicSharedMemorySize, GEMM_SMEM);

    init_kernel<<<1, 32>>>();
    router_kernel<<<NTOK / 8, 256>>>(x, Wr);
    scan_kernel<<<1, 1024>>>();

    // bf16 splits of x, W1, W2
    {
        __nv_bfloat16 *xh, *xl, *w1h, *w1l, *w2h, *w2l;
        cudaGetSymbolAddress((void**)&xh,  g_xh);
        cudaGetSymbolAddress((void**)&xl,  g_xl);
        cudaGetSymbolAddress((void**)&w1h, g_W1h);
        cudaGetSymbolAddress((void**)&w1l, g_W1l);
        cudaGetSymbolAddress((void**)&w2h, g_W2h);
        cudaGetSymbolAddress((void**)&w2l, g_W2l);
        size_t nx = (size_t)NTOK * DIM / 4;
        size_t nw = (size_t)NEXP * DIM * DFF / 4;
        split_kernel<<<(unsigned)((nx + 255) / 256), 256>>>(x,  xh,  xl,  nx);
        split_kernel<<<(unsigned)((nw + 255) / 256), 256>>>(W1, w1h, w1l, nw);
        split_kernel<<<(unsigned)((nw + 255) / 256), 256>>>(W2, w2h, w2l, nw);
    }

    // GEMM1: h = gelu(gather(x) @ W1 + b1)   [M=CAP, N=DFF, K=DIM]
    gemm_mma<DIM, DFF, 0><<<dim3(DFF / 128, CAP / 128, NEXP), 256, GEMM_SMEM>>>(b1, nullptr);

    passthrough_kernel<<<NTOK, 256>>>(x, out);

    // GEMM2: out[tok] = gate * (h @ W2 + b2) [M=CAP, N=DIM, K=DFF]
    gemm_mma<DFF, DIM, 1><<<dim3(DIM / 128, CAP / 128, NEXP), 256, GEMM_SMEM>>>(b2, out);

    aux_kernel<<<1, 1>>>(out, out_size);
}

// round 11
// speedup vs baseline: 2.6715x; 1.1826x over previous
#include <cuda_runtime.h>
#include <cuda_bf16.h>
#include <cstdint>
#include <math.h>

#define NTOK 8192
#define DIM  1024
#define NEXP 8
#define DFF  4096
#define CAP  1280   // int(8192/8 * 1.25)

// ---------------- scratch (device globals; no allocation allowed) ----------
__device__ __nv_bfloat16 g_xh[(size_t)NTOK * DIM];
__device__ __nv_bfloat16 g_xl[(size_t)NTOK * DIM];
__device__ __nv_bfloat16 g_W1h[(size_t)NEXP * DIM * DFF];
__device__ __nv_bfloat16 g_W1l[(size_t)NEXP * DIM * DFF];
__device__ __nv_bfloat16 g_W2h[(size_t)NEXP * DFF * DIM];
__device__ __nv_bfloat16 g_W2l[(size_t)NEXP * DFF * DIM];
__device__ __nv_bfloat16 g_hh[(size_t)NEXP * CAP * DFF];
__device__ __nv_bfloat16 g_hl[(size_t)NEXP * CAP * DFF];
__device__ int   g_eidx[NTOK];
__device__ float g_gate[NTOK];
__device__ int   g_kept[NTOK];
__device__ int   g_slot2tok[NEXP * CAP];
__device__ float g_probs_sum[NEXP];
__device__ int   g_count[NEXP];

// ---------------- init ------------------------------------------------------
__global__ void init_kernel() {
    if (threadIdx.x < NEXP) g_probs_sum[threadIdx.x] = 0.f;
}

// ---------------- router: logits, softmax, argmax, gate --------------------
__global__ void router_kernel(const float* __restrict__ x,
                              const float* __restrict__ Wr) {
    __shared__ float s_sum[NEXP];
    if (threadIdx.x < NEXP) s_sum[threadIdx.x] = 0.f;
    __syncthreads();

    int gwarp = (blockIdx.x * blockDim.x + threadIdx.x) >> 5;
    int lane  = threadIdx.x & 31;
    if (gwarp < NTOK) {
        const float* xr = x + (size_t)gwarp * DIM;
        float acc[NEXP];
#pragma unroll
        for (int e = 0; e < NEXP; e++) acc[e] = 0.f;
        for (int d = lane; d < DIM; d += 32) {
            float xv = xr[d];
            const float* wr = Wr + d * NEXP;
#pragma unroll
            for (int e = 0; e < NEXP; e++) acc[e] += xv * wr[e];
        }
#pragma unroll
        for (int e = 0; e < NEXP; e++)
#pragma unroll
            for (int o = 16; o; o >>= 1)
                acc[e] += __shfl_xor_sync(0xffffffffu, acc[e], o);

        if (lane == 0) {
            float mx = acc[0]; int ai = 0;
#pragma unroll
            for (int e = 1; e < NEXP; e++)
                if (acc[e] > mx) { mx = acc[e]; ai = e; }
            float p[NEXP], den = 0.f;
#pragma unroll
            for (int e = 0; e < NEXP; e++) { p[e] = expf(acc[e] - mx); den += p[e]; }
            float inv = 1.f / den;
#pragma unroll
            for (int e = 0; e < NEXP; e++) {
                p[e] *= inv;
                atomicAdd(&s_sum[e], p[e]);
            }
            g_eidx[gwarp] = ai;
            g_gate[gwarp] = p[ai];
        }
    }
    __syncthreads();
    if (threadIdx.x < NEXP) atomicAdd(&g_probs_sum[threadIdx.x], s_sum[threadIdx.x]);
}

// ---------------- scan: order-exact per-expert positions + capacity --------
__global__ void scan_kernel() {
    __shared__ int sbase[NEXP];
    __shared__ int wpre[NEXP][32];
    __shared__ int ctot[NEXP];
    int tid = threadIdx.x, lane = tid & 31, wid = tid >> 5;

    for (int i = tid; i < NEXP * CAP; i += 1024) g_slot2tok[i] = NTOK;
    if (tid < NEXP) sbase[tid] = 0;
    __syncthreads();

    for (int c0 = 0; c0 < NTOK; c0 += 1024) {
        int tok = c0 + tid;
        int e = g_eidx[tok];
        int myrank = 0;
#pragma unroll
        for (int e2 = 0; e2 < NEXP; e2++) {
            unsigned m = __ballot_sync(0xffffffffu, e == e2);
            if (e == e2) myrank = __popc(m & ((1u << lane) - 1u));
            if (lane == 0) wpre[e2][wid] = __popc(m);
        }
        __syncthreads();
        if (wid < NEXP) {
            int v = wpre[wid][lane];
            int incl = v;
#pragma unroll
            for (int o = 1; o < 32; o <<= 1) {
                int t = __shfl_up_sync(0xffffffffu, incl, o);
                if (lane >= o) incl += t;
            }
            wpre[wid][lane] = incl - v;
            if (lane == 31) ctot[wid] = incl;
        }
        __syncthreads();
        int pos  = sbase[e] + wpre[e][wid] + myrank;
        int kept = (pos < CAP) ? 1 : 0;
        g_kept[tok] = kept;
        if (kept) g_slot2tok[e * CAP + pos] = tok;
        else      g_gate[tok] = 0.f;
        __syncthreads();
        if (tid < NEXP) sbase[tid] += ctot[tid];
        __syncthreads();
    }
    if (tid < NEXP) g_count[tid] = sbase[tid] < CAP ? sbase[tid] : CAP;
}

// ---------------- bf16 split: v = hi + lo (both rn) ------------------------
__device__ __forceinline__ void bf16_split(float v, __nv_bfloat16& h, __nv_bfloat16& l) {
    h = __float2bfloat16(v);
    l = __float2bfloat16(v - __bfloat162float(h));
}

// elementwise split kernel: 4 elems/thread
__global__ void split_kernel(const float* __restrict__ src,
                             __nv_bfloat16* __restrict__ dh,
                             __nv_bfloat16* __restrict__ dl, size_t n4) {
    size_t i = (size_t)blockIdx.x * blockDim.x + threadIdx.x;
    if (i >= n4) return;
    float4 v = ((const float4*)src)[i];
    __nv_bfloat16 h0, h1, h2, h3, l0, l1, l2, l3;
    bf16_split(v.x, h0, l0);
    bf16_split(v.y, h1, l1);
    bf16_split(v.z, h2, l2);
    bf16_split(v.w, h3, l3);
    ((__nv_bfloat162*)dh)[i * 2]     = __nv_bfloat162(h0, h1);
    ((__nv_bfloat162*)dh)[i * 2 + 1] = __nv_bfloat162(h2, h3);
    ((__nv_bfloat162*)dl)[i * 2]     = __nv_bfloat162(l0, l1);
    ((__nv_bfloat162*)dl)[i * 2 + 1] = __nv_bfloat162(l2, l3);
}

// ---------------- GELU (tanh approximation) --------------------------------
__device__ __forceinline__ float gelu_tanh(float v) {
    const float k0 = 0.7978845608028654f;
    const float k1 = 0.044715f;
    float u = k0 * (v + k1 * v * v * v);
    return 0.5f * v * (1.f + tanhf(u));
}

// ============ tensor-core GEMM via 3x bf16 mma.sync (split operands) ========
// CTA tile 128(M) x 128(N) x 32(K). 256 threads = 8 warps (4m x 2n),
// warp tile 32x64 = 2 m-frags x 8 n-frags of m16n8k16.
// a*b ~= a0*b0 + a0*b1 + a1*b0 with a0,b0 bf16(rn) and a1,b1 residuals.
// 2-stage cp.async double-buffer; 2 CTAs/SM for cross-CTA latency hiding.
// MODE 0: A = gathered split-x rows -> epilogue gelu(v+b1) split into g_hh/g_hl
// MODE 1: A = split-h rows          -> epilogue gate*(v+b2) scattered to out

#define ASTR 40     // bf16 per A row (32 + 8 pad)
#define BSTR 136    // bf16 per B row (128 + 8 pad)
#define OFF_AH 0
#define OFF_AL (128 * ASTR)                  // 5120
#define OFF_BH (2 * 128 * ASTR)              // 10240
#define OFF_BL (2 * 128 * ASTR + 32 * BSTR)  // 14592
#define STAGE_ELEMS (2 * 128 * ASTR + 2 * 32 * BSTR)   // 18944 bf16 = 37888 B
#define NSTAGE 2
#define GEMM_SMEM (STAGE_ELEMS * NSTAGE * 2)           // 75776 B

__device__ __forceinline__ void cpa16(uint32_t dst, const void* src, int src_size) {
    asm volatile("cp.async.cg.shared.global [%0], [%1], 16, %2;"
                 :: "r"(dst), "l"(src), "r"(src_size));
}
__device__ __forceinline__ void cpa_commit() {
    asm volatile("cp.async.commit_group;" ::: "memory");
}
template<int N> __device__ __forceinline__ void cpa_wait() {
    asm volatile("cp.async.wait_group %0;" :: "n"(N) : "memory");
}

__device__ __forceinline__ void ldsm_x4(uint32_t* r, uint32_t a) {
    asm volatile("ldmatrix.sync.aligned.m8n8.x4.shared.b16 {%0,%1,%2,%3}, [%4];"
                 : "=r"(r[0]), "=r"(r[1]), "=r"(r[2]), "=r"(r[3]) : "r"(a));
}
__device__ __forceinline__ void ldsm_x4_t(uint32_t* r, uint32_t a) {
    asm volatile("ldmatrix.sync.aligned.m8n8.x4.trans.shared.b16 {%0,%1,%2,%3}, [%4];"
                 : "=r"(r[0]), "=r"(r[1]), "=r"(r[2]), "=r"(r[3]) : "r"(a));
}

__device__ __forceinline__ void mma_bf16(float* d, const uint32_t* a, const uint32_t* b) {
    asm volatile(
        "mma.sync.aligned.m16n8k16.row.col.f32.bf16.bf16.f32 "
        "{%0,%1,%2,%3}, {%4,%5,%6,%7}, {%8,%9}, {%0,%1,%2,%3};"
        : "+f"(d[0]), "+f"(d[1]), "+f"(d[2]), "+f"(d[3])
        : "r"(a[0]), "r"(a[1]), "r"(a[2]), "r"(a[3]), "r"(b[0]), "r"(b[1]));
}

template<int KDIM, int NB, int MODE>
__global__ __launch_bounds__(256, 2)
void gemm_mma(const float* __restrict__ bias, float* __restrict__ out) {
    extern __shared__ __align__(16) __nv_bfloat16 smem[];
    const int e  = blockIdx.z;
    const int mt = blockIdx.y;
    const int nt = blockIdx.x;
    const int tid = threadIdx.x;
    const int lane = tid & 31;
    const int wid  = tid >> 5;
    const int wm = (wid & 3) * 32;        // warp m offset
    const int wn = (wid >> 2) * 64;       // warp n offset

    // ---- per-thread global source pointers (A: 2 thr/row, B: 8 thr/row) ----
    const int arow = tid >> 1;
    const int ahalf = tid & 1;            // 16-bf16 half of the 32-chunk
    const __nv_bfloat16 *aph, *apl;
    int asz = 16;
    if (MODE == 0) {
        int tok = g_slot2tok[e * CAP + mt * 128 + arow];
        if (tok >= NTOK) { tok = 0; asz = 0; }       // zero-fill dropped slot
        aph = g_xh + (size_t)tok * DIM + ahalf * 16;
        apl = g_xl + (size_t)tok * DIM + ahalf * 16;
    } else {
        size_t off = (size_t)(e * CAP + mt * 128 + arow) * KDIM + ahalf * 16;
        aph = g_hh + off;
        apl = g_hl + off;
    }
    const size_t boff = (size_t)e * KDIM * NB + (size_t)(tid >> 3) * NB
                      + nt * 128 + (tid & 7) * 16;
    const __nv_bfloat16* bph = ((MODE == 0) ? g_W1h : g_W2h) + boff;
    const __nv_bfloat16* bpl = ((MODE == 0) ? g_W1l : g_W2l) + boff;

    const uint32_t smem_b = (uint32_t)__cvta_generic_to_shared(smem);
    const uint32_t sa = (arow * ASTR + ahalf * 16) * 2;           // bytes
    const uint32_t sb = ((tid >> 3) * BSTR + (tid & 7) * 16) * 2; // bytes

    const int NC = KDIM / 32;

    auto load_stage = [&](int s, int k0) {
        uint32_t base = smem_b + s * STAGE_ELEMS * 2;
        cpa16(base + OFF_AH * 2 + sa,      aph + k0, asz);
        cpa16(base + OFF_AH * 2 + sa + 16, aph + k0 + 8, asz);
        cpa16(base + OFF_AL * 2 + sa,      apl + k0, asz);
        cpa16(base + OFF_AL * 2 + sa + 16, apl + k0 + 8, asz);
        const __nv_bfloat16* bh = bph + (size_t)k0 * NB;
        const __nv_bfloat16* bl = bpl + (size_t)k0 * NB;
        cpa16(base + OFF_BH * 2 + sb,      bh, 16);
        cpa16(base + OFF_BH * 2 + sb + 16, bh + 8, 16);
        cpa16(base + OFF_BL * 2 + sb,      bl, 16);
        cpa16(base + OFF_BL * 2 + sb + 16, bl + 8, 16);
        cpa_commit();
    };

    load_stage(0, 0);
    load_stage(1, 32);

    // ---- ldmatrix lane addressing (stage-invariant parts) ----
    const int lr = lane & 7, lg = lane >> 3;
    // A: row = wm + mi*16 + (lg&1)*8 + lr ; col = ks*16 + (lg>>1)*8
    const int a_row = wm + (lg & 1) * 8 + lr;
    const int a_col = (lg >> 1) * 8;
    // B(trans): row(k) = ks*16 + (lg&1)*8 + lr ; col(n) = wn + nf2*16 + (lg>>1)*8
    const int b_row = (lg & 1) * 8 + lr;
    const int b_col = wn + (lg >> 1) * 8;

    float acc[2][8][4];
#pragma unroll
    for (int mi = 0; mi < 2; mi++)
#pragma unroll
        for (int nf = 0; nf < 8; nf++)
#pragma unroll
            for (int q = 0; q < 4; q++) acc[mi][nf][q] = 0.f;

    for (int c = 0; c < NC; c++) {
        cpa_wait<1>();
        __syncthreads();

        uint32_t base = smem_b + (c & 1) * STAGE_ELEMS * 2;

#pragma unroll
        for (int ks = 0; ks < 2; ks++) {
            uint32_t ah[2][4], al[2][4];
#pragma unroll
            for (int mi = 0; mi < 2; mi++) {
                uint32_t addr = base +
                    ((a_row + mi * 16) * ASTR + ks * 16 + a_col) * 2;
                ldsm_x4(ah[mi], addr + OFF_AH * 2);
                ldsm_x4(al[mi], addr + OFF_AL * 2);
            }
            // B processed one hi/lo ldmatrix group (2 nf) at a time: low regs
#pragma unroll
            for (int nf2 = 0; nf2 < 4; nf2++) {
                uint32_t addr = base +
                    ((ks * 16 + b_row) * BSTR + b_col + nf2 * 16) * 2;
                uint32_t rh[4], rl[4];
                ldsm_x4_t(rh, addr + OFF_BH * 2);
                ldsm_x4_t(rl, addr + OFF_BL * 2);
#pragma unroll
                for (int mi = 0; mi < 2; mi++) {
                    mma_bf16(acc[mi][nf2 * 2],     ah[mi], rh);
                    mma_bf16(acc[mi][nf2 * 2 + 1], ah[mi], rh + 2);
                }
#pragma unroll
                for (int mi = 0; mi < 2; mi++) {
                    mma_bf16(acc[mi][nf2 * 2],     ah[mi], rl);
                    mma_bf16(acc[mi][nf2 * 2 + 1], ah[mi], rl + 2);
                }
#pragma unroll
                for (int mi = 0; mi < 2; mi++) {
                    mma_bf16(acc[mi][nf2 * 2],     al[mi], rh);
                    mma_bf16(acc[mi][nf2 * 2 + 1], al[mi], rh + 2);
                }
            }
        }
        __syncthreads();
        // refill the buffer just consumed with chunk c+2
        if (c + 2 < NC) load_stage(c & 1, (c + 2) * 32);
        else            cpa_commit();
    }

    // ---- epilogue ----
    const float* bias_p = bias + e * NB + nt * 128;
#pragma unroll
    for (int mi = 0; mi < 2; mi++) {
#pragma unroll
        for (int rr = 0; rr < 2; rr++) {
            int lrow = wm + mi * 16 + (lane >> 2) + rr * 8;   // row in tile
            int slot = e * CAP + mt * 128 + lrow;
            if (MODE == 0) {
                size_t rowoff = (size_t)slot * DFF + nt * 128;
#pragma unroll
                for (int nf = 0; nf < 8; nf++) {
                    int cn = wn + nf * 8 + (lane & 3) * 2;
                    float v0 = gelu_tanh(acc[mi][nf][rr * 2 + 0] + bias_p[cn]);
                    float v1 = gelu_tanh(acc[mi][nf][rr * 2 + 1] + bias_p[cn + 1]);
                    __nv_bfloat16 h0, h1, l0, l1;
                    bf16_split(v0, h0, l0);
                    bf16_split(v1, h1, l1);
                    *(__nv_bfloat162*)(g_hh + rowoff + cn) = __nv_bfloat162(h0, h1);
                    *(__nv_bfloat162*)(g_hl + rowoff + cn) = __nv_bfloat162(l0, l1);
                }
            } else {
                int tok = g_slot2tok[slot];
                if (tok < NTOK) {
                    float gt = g_gate[tok];
                    float* orow = out + (size_t)tok * DIM + nt * 128;
#pragma unroll
                    for (int nf = 0; nf < 8; nf++) {
                        int cn = wn + nf * 8 + (lane & 3) * 2;
                        float2 v;
                        v.x = gt * (acc[mi][nf][rr * 2 + 0] + bias_p[cn]);
                        v.y = gt * (acc[mi][nf][rr * 2 + 1] + bias_p[cn + 1]);
                        *(float2*)(orow + cn) = v;
                    }
                }
            }
        }
    }
}

// ---------------- passthrough for dropped tokens ---------------------------
__global__ void passthrough_kernel(const float* __restrict__ x,
                                   float* __restrict__ out) {
    int tok = blockIdx.x;
    if (g_kept[tok]) return;
    const float4* src = (const float4*)(x + (size_t)tok * DIM);
    float4* dst = (float4*)(out + (size_t)tok * DIM);
    dst[threadIdx.x] = src[threadIdx.x];
}

// ---------------- aux loss --------------------------------------------------
__global__ void aux_kernel(float* __restrict__ out, int out_size) {
    if (out_size <= NTOK * DIM) return;
    float s = 0.f;
    for (int e = 0; e < NEXP; e++) {
        float frac = (float)g_count[e] / (float)NTOK;
        float pm   = g_probs_sum[e] / (float)NTOK;
        s += frac * pm;
    }
    out[NTOK * DIM] = 0.01f * (float)NEXP * s;
}

// ---------------- launch ----------------------------------------------------
extern "C" void kernel_launch(void* const* d_in, const int* in_sizes, int n_in,
                              void* d_out, int out_size) {
    const float* x  = (const float*)d_in[0];
    const float* Wr = (const float*)d_in[1];
    const float* W1 = (const float*)d_in[2];
    const float* b1 = (const float*)d_in[3];
    const float* W2 = (const float*)d_in[4];
    const float* b2 = (const float*)d_in[5];
    float* out = (float*)d_out;

    cudaFuncSetAttribute(gemm_mma<DIM, DFF, 0>,
                         cudaFuncAttributeMaxDynamicSharedMemorySize, GEMM_SMEM);
    cudaFuncSetAttribute(gemm_mma<DFF, DIM, 1>,
                         cudaFuncAttributeMaxDynamicSharedMemorySize, GEMM_SMEM);

    init_kernel<<<1, 32>>>();
    router_kernel<<<NTOK / 8, 256>>>(x, Wr);
    scan_kernel<<<1, 1024>>>();

    // bf16 splits of x, W1, W2
    {
        __nv_bfloat16 *xh, *xl, *w1h, *w1l, *w2h, *w2l;
        cudaGetSymbolAddress((void**)&xh,  g_xh);
        cudaGetSymbolAddress((void**)&xl,  g_xl);
        cudaGetSymbolAddress((void**)&w1h, g_W1h);
        cudaGetSymbolAddress((void**)&w1l, g_W1l);
        cudaGetSymbolAddress((void**)&w2h, g_W2h);
        cudaGetSymbolAddress((void**)&w2l, g_W2l);
        size_t nx = (size_t)NTOK * DIM / 4;
        size_t nw = (size_t)NEXP * DIM * DFF / 4;
        split_kernel<<<(unsigned)((nx + 255) / 256), 256>>>(x,  xh,  xl,  nx);
        split_kernel<<<(unsigned)((nw + 255) / 256), 256>>>(W1, w1h, w1l, nw);
        split_kernel<<<(unsigned)((nw + 255) / 256), 256>>>(W2, w2h, w2l, nw);
    }

    // GEMM1: h = gelu(gather(x) @ W1 + b1)   [M=CAP, N=DFF, K=DIM]
    gemm_mma<DIM, DFF, 0><<<dim3(DFF / 128, CAP / 128, NEXP), 256, GEMM_SMEM>>>(b1, nullptr);

    passthrough_kernel<<<NTOK, 256>>>(x, out);

    // GEMM2: out[tok] = gate * (h @ W2 + b2) [M=CAP, N=DIM, K=DFF]
    gemm_mma<DFF, DIM, 1><<<dim3(DIM / 128, CAP / 128, NEXP), 256, GEMM_SMEM>>>(b2, out);

    aux_kernel<<<1, 1>>>(out, out_size);
}